// round 1
// baseline (speedup 1.0000x reference)
#include <cuda_runtime.h>
#include <math.h>

#define N_NODES 1024
#define C_DIM   128
#define H_HEADS 8
#define D_HEAD  16
#define E_EDGES 32768
#define NN      (N_NODES * N_NODES)
#define SEQ_MAX 512

// Scratch (device globals; no allocation allowed)
__device__ float g_adj[3 * NN];            // 12 MB scatter target
__device__ float g_conv[NN];               // 4 MB conv_out
__device__ float g_Q[N_NODES * C_DIM];
__device__ float g_K[N_NODES * C_DIM];
__device__ float g_V[N_NODES * C_DIM];
__device__ float g_P[SEQ_MAX * C_DIM];     // positional table: P[s,:] = PE(s)@Wpos.T + bpos
__device__ float g_outpre[N_NODES * C_DIM];

// ---------------------------------------------------------------------------
__global__ void zero_adj_kernel() {
    int i = blockIdx.x * blockDim.x + threadIdx.x;   // over 3*NN/4 float4s
    ((float4*)g_adj)[i] = make_float4(0.f, 0.f, 0.f, 0.f);
}

__global__ void scatter_edges_kernel(const int* __restrict__ ei,
                                     const float* __restrict__ sign,
                                     const float* __restrict__ w) {
    int e = blockIdx.x * blockDim.x + threadIdx.x;
    if (e >= E_EDGES) return;
    int r = ei[e];
    int c = ei[E_EDGES + e];
    float* base = g_adj + ((size_t)r * N_NODES + c) * 3;
    atomicAdd(base + 0, sign[2 * e]);
    atomicAdd(base + 1, sign[2 * e + 1]);
    atomicAdd(base + 2, w[e]);
}

// conv_out_flat[p] = sum_c conv_w[c] * adjflat[c*NN + p] + conv_b
__global__ void conv_kernel(const float* __restrict__ cw, const float* __restrict__ cb) {
    int i = blockIdx.x * blockDim.x + threadIdx.x;   // over NN/4 float4s
    float w0 = cw[0], w1 = cw[1], w2 = cw[2], b = cb[0];
    float4 a0 = ((const float4*)g_adj)[i];
    float4 a1 = ((const float4*)(g_adj + NN))[i];
    float4 a2 = ((const float4*)(g_adj + 2 * NN))[i];
    float4 o;
    o.x = w0 * a0.x + w1 * a1.x + w2 * a2.x + b;
    o.y = w0 * a0.y + w1 * a1.y + w2 * a2.y + b;
    o.z = w0 * a0.z + w1 * a1.z + w2 * a2.z + b;
    o.w = w0 * a0.w + w1 * a1.w + w2 * a2.w + b;
    ((float4*)g_conv)[i] = o;
}

// Q/K/V = x @ W.T   (one block per node, one thread per output channel)
__global__ void qkv_kernel(const float* __restrict__ x,
                           const float* __restrict__ Wq,
                           const float* __restrict__ Wk,
                           const float* __restrict__ Wv) {
    int n = blockIdx.x;
    int c = threadIdx.x;
    __shared__ float xr[C_DIM];
    xr[c] = x[n * C_DIM + c];
    __syncthreads();
    const float4* wq = (const float4*)(Wq + c * C_DIM);
    const float4* wk = (const float4*)(Wk + c * C_DIM);
    const float4* wv = (const float4*)(Wv + c * C_DIM);
    float q = 0.f, k = 0.f, v = 0.f;
#pragma unroll
    for (int t = 0; t < C_DIM / 4; t++) {
        float4 xv = ((const float4*)xr)[t];
        float4 a = wq[t];
        q += xv.x * a.x + xv.y * a.y + xv.z * a.z + xv.w * a.w;
        float4 bq = wk[t];
        k += xv.x * bq.x + xv.y * bq.y + xv.z * bq.z + xv.w * bq.w;
        float4 cv = wv[t];
        v += xv.x * cv.x + xv.y * cv.y + xv.z * cv.z + xv.w * cv.w;
    }
    g_Q[n * C_DIM + c] = q;
    g_K[n * C_DIM + c] = k;
    g_V[n * C_DIM + c] = v;
}

// P[s, c] = bpos[c] + sum_{c'} PE(s, c') * Wpos[c, c']
// PE(s, c') = sin(s * invf[c'])       for c' < 64
//           = cos(s * invf[c' - 64])  for c' >= 64
// invf[j] = 10000^(-j/64)
__global__ void ptable_kernel(const float* __restrict__ Wpos,
                              const float* __restrict__ bpos) {
    int s = blockIdx.x;
    int c = threadIdx.x;
    __shared__ float pe[C_DIM];
    if (c < 64) {
        float invf = (float)exp(-log(10000.0) * (double)c / 64.0);
        float arg = (float)s * invf;
        pe[c] = sinf(arg);
        pe[c + 64] = cosf(arg);
    }
    __syncthreads();
    const float4* wr = (const float4*)(Wpos + c * C_DIM);
    float acc = bpos[c];
#pragma unroll
    for (int t = 0; t < C_DIM / 4; t++) {
        float4 p = ((const float4*)pe)[t];
        float4 w = wr[t];
        acc += p.x * w.x + p.y * w.y + p.z * w.z + p.w * w.w;
    }
    g_P[s * C_DIM + c] = acc;
}

// Main attention: one block per (h, a) row. 256 threads.
// logits[b] = (q.k_b + q.P[seq]) / sqrt(C) + param * conv[a, b]
// softmax over b, write attn row, accumulate out_r[h,a,:] = attn . V
__global__ void attn_kernel(const int* __restrict__ seq,
                            const float* __restrict__ param,
                            float* __restrict__ attn_out) {
    int blk = blockIdx.x;
    int h = blk >> 10;
    int a = blk & 1023;
    int tid = threadIdx.x;

    __shared__ float qs[D_HEAD];
    __shared__ int srow[128];
    __shared__ float attns[N_NODES];
    __shared__ float red[256];
    __shared__ float part[16][17];

    if (tid < D_HEAD) qs[tid] = g_Q[h * 16384 + a * D_HEAD + tid];
    int i = h * 128 + (a >> 3);
    int arow = a & 7;
    if (tid < 128) srow[tid] = seq[i * N_NODES + arow * 128 + tid];
    __syncthreads();

    float q[D_HEAD];
#pragma unroll
    for (int d = 0; d < D_HEAD; d++) q[d] = qs[d];

    const float SCALE = 0.0883883476483184f;  // 1/sqrt(128)
    float prm = param[0];
    float lv[4];
    float lmax = -1e30f;
#pragma unroll
    for (int t = 0; t < 4; t++) {
        int b = tid + t * 256;
        int s = srow[b >> 3];
        const float4* kr = (const float4*)(g_K + h * 16384 + b * D_HEAD);
        const float4* pr = (const float4*)(g_P + s * C_DIM + (b & 7) * D_HEAD);
        float cont = 0.f, pos = 0.f;
#pragma unroll
        for (int u = 0; u < 4; u++) {
            float4 kv = kr[u];
            float4 pv = pr[u];
            cont += q[4 * u] * kv.x + q[4 * u + 1] * kv.y + q[4 * u + 2] * kv.z + q[4 * u + 3] * kv.w;
            pos  += q[4 * u] * pv.x + q[4 * u + 1] * pv.y + q[4 * u + 2] * pv.z + q[4 * u + 3] * pv.w;
        }
        float lg = (cont + pos) * SCALE + prm * g_conv[a * N_NODES + b];
        lv[t] = lg;
        lmax = fmaxf(lmax, lg);
    }
    // block max
    red[tid] = lmax;
    __syncthreads();
    for (int s2 = 128; s2 > 0; s2 >>= 1) {
        if (tid < s2) red[tid] = fmaxf(red[tid], red[tid + s2]);
        __syncthreads();
    }
    float gmax = red[0];
    __syncthreads();
    // exp + sum
    float esum = 0.f;
#pragma unroll
    for (int t = 0; t < 4; t++) {
        int b = tid + t * 256;
        float e = expf(lv[t] - gmax);
        attns[b] = e;
        esum += e;
    }
    red[tid] = esum;
    __syncthreads();
    for (int s2 = 128; s2 > 0; s2 >>= 1) {
        if (tid < s2) red[tid] += red[tid + s2];
        __syncthreads();
    }
    float inv = 1.0f / red[0];
    float* aout = attn_out + (size_t)h * NN + (size_t)a * N_NODES;
#pragma unroll
    for (int t = 0; t < 4; t++) {
        int b = tid + t * 256;
        float v = attns[b] * inv;
        attns[b] = v;
        aout[b] = v;
    }
    __syncthreads();
    // out_r[h,a,d] = sum_b attn[b] * V[h,b,d]
    int d = tid & 15;
    int bg = tid >> 4;
    float acc = 0.f;
#pragma unroll 8
    for (int t = 0; t < 64; t++) {
        int b = bg + t * 16;
        acc += attns[b] * g_V[h * 16384 + b * D_HEAD + d];
    }
    part[bg][d] = acc;
    __syncthreads();
    if (tid < 16) {
        float s2 = 0.f;
#pragma unroll
        for (int g2 = 0; g2 < 16; g2++) s2 += part[g2][tid];
        g_outpre[h * 16384 + a * D_HEAD + tid] = s2;
    }
}

// out = outpre @ Wout.T
__global__ void outgemm_kernel(const float* __restrict__ Wout, float* __restrict__ out) {
    int n = blockIdx.x;
    int c = threadIdx.x;
    __shared__ float r[C_DIM];
    r[c] = g_outpre[n * C_DIM + c];
    __syncthreads();
    const float4* w = (const float4*)(Wout + c * C_DIM);
    float acc = 0.f;
#pragma unroll
    for (int t = 0; t < C_DIM / 4; t++) {
        float4 xv = ((const float4*)r)[t];
        float4 wv = w[t];
        acc += xv.x * wv.x + xv.y * wv.y + xv.z * wv.z + xv.w * wv.w;
    }
    out[n * C_DIM + c] = acc;
}

// ---------------------------------------------------------------------------
extern "C" void kernel_launch(void* const* d_in, const int* in_sizes, int n_in,
                              void* d_out, int out_size) {
    const float* x      = (const float*)d_in[0];
    const float* sign   = (const float*)d_in[1];
    const float* weight = (const float*)d_in[2];
    const float* Wq     = (const float*)d_in[3];
    const float* Wk     = (const float*)d_in[4];
    const float* Wv     = (const float*)d_in[5];
    const float* Wout   = (const float*)d_in[6];
    const float* Wpos   = (const float*)d_in[7];
    const float* bpos   = (const float*)d_in[8];
    const float* conv_w = (const float*)d_in[9];
    const float* conv_b = (const float*)d_in[10];
    const float* param  = (const float*)d_in[11];
    const int*   seq    = (const int*)d_in[12];
    const int*   ei     = (const int*)d_in[13];

    float* out  = (float*)d_out;              // [1024, 128]
    float* attn = out + N_NODES * C_DIM;      // [1, 8, 1024, 1024]

    zero_adj_kernel<<<(3 * NN / 4) / 256, 256>>>();
    scatter_edges_kernel<<<E_EDGES / 256, 256>>>(ei, sign, weight);
    conv_kernel<<<(NN / 4) / 256, 256>>>(conv_w, conv_b);
    qkv_kernel<<<N_NODES, C_DIM>>>(x, Wq, Wk, Wv);
    ptable_kernel<<<SEQ_MAX, C_DIM>>>(Wpos, bpos);
    attn_kernel<<<H_HEADS * N_NODES, 256>>>(seq, param, attn);
    outgemm_kernel<<<N_NODES, C_DIM>>>(Wout, out);
}

// round 2
// speedup vs baseline: 1.5831x; 1.5831x over previous
#include <cuda_runtime.h>
#include <math.h>

#define N_NODES 1024
#define C_DIM   128
#define H_HEADS 8
#define D_HEAD  16
#define E_EDGES 32768
#define NN      (N_NODES * N_NODES)
#define SEQ_MAX 512

// Scratch (device globals; no allocation allowed)
__device__ float g_conv[NN];               // fused conv output (scatter target)
__device__ float g_Q[N_NODES * C_DIM];
__device__ float g_K[N_NODES * C_DIM];
__device__ float g_V[N_NODES * C_DIM];
__device__ float g_PE[SEQ_MAX * C_DIM];    // raw sinusoid table
__device__ float g_P[SEQ_MAX * C_DIM];     // P[s,:] = PE(s)@Wpos.T + bpos
__device__ float g_outpre[N_NODES * C_DIM];

// ---------------------------------------------------------------------------
__global__ void zero_conv_kernel() {
    int i = blockIdx.x * blockDim.x + threadIdx.x;   // NN/4 float4s
    ((float4*)g_conv)[i] = make_float4(0.f, 0.f, 0.f, 0.f);
}

// Fused scatter + 1x1 conv: adjflat[f] with f = 3*(r*1024+c)+t contributes
// conv_w[f/NN] * val at conv position f % NN.
__global__ void scatter_conv_kernel(const int* __restrict__ ei,
                                    const float* __restrict__ sign,
                                    const float* __restrict__ w,
                                    const float* __restrict__ cw) {
    int e = blockIdx.x * blockDim.x + threadIdx.x;
    if (e >= E_EDGES) return;
    int r = ei[e];
    int c = ei[E_EDGES + e];
    float vals[3] = { sign[2 * e], sign[2 * e + 1], w[e] };
    unsigned f0 = 3u * ((unsigned)r * N_NODES + (unsigned)c);
#pragma unroll
    for (int t = 0; t < 3; t++) {
        unsigned f = f0 + t;
        atomicAdd(g_conv + (f & (NN - 1)), cw[f >> 20] * vals[t]);
    }
}

// PE[s, c]: c<64 -> sin(s * invf[c]); c>=64 -> cos(s * invf[c-64])
__global__ void pe_kernel() {
    int idx = blockIdx.x * blockDim.x + threadIdx.x;   // 65536
    int s = idx >> 7;
    int c = idx & 127;
    int j = (c < 64) ? c : c - 64;
    // invf = 10000^(-j/64) = 2^(-j * log2(10000)/64)
    float invf = exp2f(-(float)j * 0.2076205059280929f);
    float arg = (float)s * invf;
    g_PE[idx] = (c < 64) ? sinf(arg) : cosf(arg);
}

// ---------------------------------------------------------------------------
// Tiled GEMM: O[n, c] = (bias? bias[c] : 0) + sum_k A[n,k] * W[c,k]
// A: [*, 128] row-major, W: [128, 128] row-major. 32x32 tile, 256 threads.
__device__ __forceinline__ void gemm128_tile(const float* __restrict__ A,
                                             const float* __restrict__ W,
                                             const float* __restrict__ bias,
                                             float* __restrict__ O) {
    __shared__ float As[32][128];
    __shared__ float Ws[32][128];
    int tid = threadIdx.x;
    int n0 = blockIdx.x * 32;
    int c0 = blockIdx.y * 32;
#pragma unroll
    for (int j = 0; j < 4; j++) {
        int f4 = tid + j * 256;          // 1024 float4s per tile
        int i = f4 >> 5;
        int k4 = f4 & 31;
        ((float4*)As)[f4] = ((const float4*)(A + (size_t)(n0 + i) * C_DIM))[k4];
        ((float4*)Ws)[f4] = ((const float4*)(W + (size_t)(c0 + i) * C_DIM))[k4];
    }
    __syncthreads();
    int tx = tid & 15;                   // col pair
    int ty = tid >> 4;                   // row pair
    float acc[2][2];
#pragma unroll
    for (int i = 0; i < 2; i++)
#pragma unroll
        for (int j = 0; j < 2; j++)
            acc[i][j] = bias ? bias[c0 + tx * 2 + j] : 0.f;
#pragma unroll
    for (int k4 = 0; k4 < 32; k4++) {
        float4 xa[2], wb[2];
#pragma unroll
        for (int i = 0; i < 2; i++) xa[i] = *(const float4*)&As[ty * 2 + i][k4 * 4];
#pragma unroll
        for (int j = 0; j < 2; j++) wb[j] = *(const float4*)&Ws[tx * 2 + j][k4 * 4];
#pragma unroll
        for (int i = 0; i < 2; i++)
#pragma unroll
            for (int j = 0; j < 2; j++)
                acc[i][j] += xa[i].x * wb[j].x + xa[i].y * wb[j].y +
                             xa[i].z * wb[j].z + xa[i].w * wb[j].w;
    }
#pragma unroll
    for (int i = 0; i < 2; i++)
#pragma unroll
        for (int j = 0; j < 2; j++)
            O[(size_t)(n0 + ty * 2 + i) * C_DIM + c0 + tx * 2 + j] = acc[i][j];
}

__global__ void qkv_gemm_kernel(const float* __restrict__ x,
                                const float* __restrict__ Wq,
                                const float* __restrict__ Wk,
                                const float* __restrict__ Wv) {
    const float* W = (blockIdx.z == 0) ? Wq : (blockIdx.z == 1) ? Wk : Wv;
    float* O = (blockIdx.z == 0) ? g_Q : (blockIdx.z == 1) ? g_K : g_V;
    gemm128_tile(x, W, nullptr, O);
}

__global__ void ptable_gemm_kernel(const float* __restrict__ Wpos,
                                   const float* __restrict__ bpos) {
    gemm128_tile(g_PE, Wpos, bpos, g_P);
}

__global__ void out_gemm_kernel(const float* __restrict__ Wout,
                                float* __restrict__ out) {
    gemm128_tile(g_outpre, Wout, nullptr, out);
}

// ---------------------------------------------------------------------------
// Attention: one block per (h, a-group of 8). 256 threads.
__global__ void attn_kernel(const int* __restrict__ seq,
                            const float* __restrict__ param,
                            const float* __restrict__ conv_b,
                            float* __restrict__ attn_out) {
    int h = blockIdx.x >> 7;
    int ag = blockIdx.x & 127;
    int a0 = ag * 8;
    int tid = threadIdx.x;
    int lane = tid & 31;
    int wid = tid >> 5;

    __shared__ float4 qs4[8][4];        // 8 q vectors (16 floats each)
    __shared__ int   srow[1024];        // full seq row i
    __shared__ float probs[8][1024];    // 32KB: logits -> exp values
    __shared__ float wred[8][8];
    __shared__ float gmaxs[8];
    __shared__ float ginv[8];
    __shared__ float4 part4[8][8][4];   // [warp][r][d4]

    if (tid < 128) ((float*)qs4)[tid] = g_Q[h * 16384 + a0 * D_HEAD + tid];
    {
        int i = h * 128 + ag;
#pragma unroll
        for (int j = 0; j < 4; j++)
            srow[tid + j * 256] = seq[(size_t)i * N_NODES + tid + j * 256];
    }
    __syncthreads();

    const float SCALE = 0.0883883476483184f;  // 1/sqrt(128)
    float prm = param[0];
    float cb  = conv_b[0];
    float lmax[8];
#pragma unroll
    for (int r = 0; r < 8; r++) lmax[r] = -1e30f;

    const float4* Kh = (const float4*)(g_K + h * 16384);
#pragma unroll
    for (int t = 0; t < 4; t++) {
        int b = tid + t * 256;
        float4 k0 = Kh[b * 4 + 0], k1 = Kh[b * 4 + 1];
        float4 k2 = Kh[b * 4 + 2], k3 = Kh[b * 4 + 3];
        int oct = b >> 3;
        int seg = (b & 7) * 4;           // float4 offset within P row
#pragma unroll
        for (int r = 0; r < 8; r++) {
            int s = srow[r * 128 + oct];
            const float4* pr = (const float4*)(g_P + s * C_DIM) + seg;
            float4 p0 = pr[0], p1 = pr[1], p2 = pr[2], p3 = pr[3];
            float4 q0 = qs4[r][0], q1 = qs4[r][1], q2 = qs4[r][2], q3 = qs4[r][3];
            float cont = q0.x*k0.x + q0.y*k0.y + q0.z*k0.z + q0.w*k0.w
                       + q1.x*k1.x + q1.y*k1.y + q1.z*k1.z + q1.w*k1.w
                       + q2.x*k2.x + q2.y*k2.y + q2.z*k2.z + q2.w*k2.w
                       + q3.x*k3.x + q3.y*k3.y + q3.z*k3.z + q3.w*k3.w;
            float pos  = q0.x*p0.x + q0.y*p0.y + q0.z*p0.z + q0.w*p0.w
                       + q1.x*p1.x + q1.y*p1.y + q1.z*p1.z + q1.w*p1.w
                       + q2.x*p2.x + q2.y*p2.y + q2.z*p2.z + q2.w*p2.w
                       + q3.x*p3.x + q3.y*p3.y + q3.z*p3.z + q3.w*p3.w;
            float cv = g_conv[(size_t)(a0 + r) * N_NODES + b];
            float lg = (cont + pos) * SCALE + prm * (cv + cb);
            probs[r][b] = lg;
            lmax[r] = fmaxf(lmax[r], lg);
        }
    }
    // block max per r
#pragma unroll
    for (int r = 0; r < 8; r++) {
        float v = lmax[r];
#pragma unroll
        for (int o = 16; o > 0; o >>= 1) v = fmaxf(v, __shfl_xor_sync(~0u, v, o));
        if (lane == 0) wred[r][wid] = v;
    }
    __syncthreads();
    if (tid < 64) {
        int r = tid >> 3, k = tid & 7;
        float v = wred[r][k];
#pragma unroll
        for (int o = 4; o > 0; o >>= 1) v = fmaxf(v, __shfl_xor_sync(~0u, v, o));
        if (k == 0) gmaxs[r] = v;
    }
    __syncthreads();

    // exp + sum
    float lsum[8];
#pragma unroll
    for (int r = 0; r < 8; r++) lsum[r] = 0.f;
#pragma unroll
    for (int t = 0; t < 4; t++) {
        int b = tid + t * 256;
#pragma unroll
        for (int r = 0; r < 8; r++) {
            float e = __expf(probs[r][b] - gmaxs[r]);
            probs[r][b] = e;
            lsum[r] += e;
        }
    }
#pragma unroll
    for (int r = 0; r < 8; r++) {
        float v = lsum[r];
#pragma unroll
        for (int o = 16; o > 0; o >>= 1) v += __shfl_xor_sync(~0u, v, o);
        if (lane == 0) wred[r][wid] = v;
    }
    __syncthreads();
    if (tid < 64) {
        int r = tid >> 3, k = tid & 7;
        float v = wred[r][k];
#pragma unroll
        for (int o = 4; o > 0; o >>= 1) v += __shfl_xor_sync(~0u, v, o);
        if (k == 0) ginv[r] = 1.f / v;
    }
    __syncthreads();

    // write normalized attn rows (probs keeps unnormalized e for V phase)
    float inv[8];
#pragma unroll
    for (int r = 0; r < 8; r++) inv[r] = ginv[r];
    float* aout = attn_out + ((size_t)h << 20) + ((size_t)a0 << 10);
#pragma unroll
    for (int t = 0; t < 4; t++) {
        int b = tid + t * 256;
#pragma unroll
        for (int r = 0; r < 8; r++)
            aout[((size_t)r << 10) + b] = probs[r][b] * inv[r];
    }

    // V phase: thread (bg, d4), bg = tid>>2 in [0,64), d4 = tid&3
    int d4 = tid & 3;
    int bg = tid >> 2;
    float4 acc[8];
#pragma unroll
    for (int r = 0; r < 8; r++) acc[r] = make_float4(0.f, 0.f, 0.f, 0.f);
    const float4* Vh = (const float4*)(g_V + h * 16384);
#pragma unroll
    for (int t = 0; t < 16; t++) {
        int b = bg + t * 64;
        float4 v4 = Vh[b * 4 + d4];
#pragma unroll
        for (int r = 0; r < 8; r++) {
            float e = probs[r][b];
            acc[r].x += e * v4.x; acc[r].y += e * v4.y;
            acc[r].z += e * v4.z; acc[r].w += e * v4.w;
        }
    }
    // reduce over bg-in-warp (lane bits 2..4) via shfl
#pragma unroll
    for (int r = 0; r < 8; r++) {
#pragma unroll
        for (int o = 16; o >= 4; o >>= 1) {
            acc[r].x += __shfl_xor_sync(~0u, acc[r].x, o);
            acc[r].y += __shfl_xor_sync(~0u, acc[r].y, o);
            acc[r].z += __shfl_xor_sync(~0u, acc[r].z, o);
            acc[r].w += __shfl_xor_sync(~0u, acc[r].w, o);
        }
    }
    if (lane < 4) {
#pragma unroll
        for (int r = 0; r < 8; r++) part4[wid][r][d4] = acc[r];
    }
    __syncthreads();
    if (tid < 128) {
        int r = tid >> 4, d = tid & 15;
        int dq = d >> 2, cmp = d & 3;
        float s = 0.f;
#pragma unroll
        for (int w = 0; w < 8; w++) s += ((const float*)&part4[w][r][dq])[cmp];
        g_outpre[h * 16384 + (a0 + r) * D_HEAD + d] = s * ginv[r];
    }
}

// ---------------------------------------------------------------------------
extern "C" void kernel_launch(void* const* d_in, const int* in_sizes, int n_in,
                              void* d_out, int out_size) {
    const float* x      = (const float*)d_in[0];
    const float* sign   = (const float*)d_in[1];
    const float* weight = (const float*)d_in[2];
    const float* Wq     = (const float*)d_in[3];
    const float* Wk     = (const float*)d_in[4];
    const float* Wv     = (const float*)d_in[5];
    const float* Wout   = (const float*)d_in[6];
    const float* Wpos   = (const float*)d_in[7];
    const float* bpos   = (const float*)d_in[8];
    const float* conv_w = (const float*)d_in[9];
    const float* conv_b = (const float*)d_in[10];
    const float* param  = (const float*)d_in[11];
    const int*   seq    = (const int*)d_in[12];
    const int*   ei     = (const int*)d_in[13];

    float* out  = (float*)d_out;              // [1024, 128]
    float* attn = out + N_NODES * C_DIM;      // [1, 8, 1024, 1024]

    zero_conv_kernel<<<NN / 4 / 256, 256>>>();
    pe_kernel<<<SEQ_MAX * C_DIM / 256, 256>>>();
    scatter_conv_kernel<<<E_EDGES / 256, 256>>>(ei, sign, weight, conv_w);
    qkv_gemm_kernel<<<dim3(32, 4, 3), 256>>>(x, Wq, Wk, Wv);
    ptable_gemm_kernel<<<dim3(16, 4), 256>>>(Wpos, bpos);
    attn_kernel<<<H_HEADS * 128, 256>>>(seq, param, conv_b, attn);
    out_gemm_kernel<<<dim3(32, 4), 256>>>(Wout, out);
}

// round 4
// speedup vs baseline: 1.8779x; 1.1863x over previous
#include <cuda_runtime.h>
#include <math.h>

#define N_NODES 1024
#define C_DIM   128
#define H_HEADS 8
#define D_HEAD  16
#define E_EDGES 32768
#define NN      (N_NODES * N_NODES)
#define SEQ_MAX 512

// Scratch (device globals; no allocation allowed)
__device__ float g_conv[NN];               // fused conv output (scatter target)
__device__ float g_Q[N_NODES * C_DIM];
__device__ float g_K[N_NODES * C_DIM];
__device__ float g_V[N_NODES * C_DIM];
__device__ float g_PE[SEQ_MAX * C_DIM];    // raw sinusoid table
__device__ float g_P[SEQ_MAX * C_DIM];     // P[s,:] = PE(s)@Wpos.T + bpos
__device__ float g_outpre[N_NODES * C_DIM];

// ---------------------------------------------------------------------------
__global__ void zero_conv_kernel() {
    int i = blockIdx.x * blockDim.x + threadIdx.x;   // NN/4 float4s
    ((float4*)g_conv)[i] = make_float4(0.f, 0.f, 0.f, 0.f);
}

// Fused scatter + 1x1 conv: adjflat[f] with f = 3*(r*1024+c)+t contributes
// conv_w[f/NN] * val at conv position f % NN.
__global__ void scatter_conv_kernel(const int* __restrict__ ei,
                                    const float* __restrict__ sign,
                                    const float* __restrict__ w,
                                    const float* __restrict__ cw) {
    int e = blockIdx.x * blockDim.x + threadIdx.x;
    if (e >= E_EDGES) return;
    int r = ei[e];
    int c = ei[E_EDGES + e];
    float vals[3] = { sign[2 * e], sign[2 * e + 1], w[e] };
    unsigned f0 = 3u * ((unsigned)r * N_NODES + (unsigned)c);
#pragma unroll
    for (int t = 0; t < 3; t++) {
        unsigned f = f0 + t;
        atomicAdd(g_conv + (f & (NN - 1)), cw[f >> 20] * vals[t]);
    }
}

// PE[s, c]: c<64 -> sin(s * invf[c]); c>=64 -> cos(s * invf[c-64])
__global__ void pe_kernel() {
    int idx = blockIdx.x * blockDim.x + threadIdx.x;   // 65536
    int s = idx >> 7;
    int c = idx & 127;
    int j = (c < 64) ? c : c - 64;
    float invf = exp2f(-(float)j * 0.2076205059280929f);  // 10000^(-j/64)
    float arg = (float)s * invf;
    g_PE[idx] = (c < 64) ? sinf(arg) : cosf(arg);
}

// ---------------------------------------------------------------------------
// SGEMM: O[n, c] = (bias? bias[c] : 0) + sum_k A[n,k] * W[c,k]
// 64x64 block tile, 4x4 register tile, K=128 in two 64-chunks.
// smem k-major with pad-to-68 rows: conflict-free a-broadcast, 2-way max on b.
#define KPAD 68
__device__ __forceinline__ void gemm64_tile(const float* __restrict__ A,
                                            const float* __restrict__ W,
                                            const float* __restrict__ bias,
                                            float* __restrict__ O) {
    __shared__ float As[64][KPAD];
    __shared__ float Ws[64][KPAD];
    int tid = threadIdx.x;
    int n0 = blockIdx.x * 64;
    int c0 = blockIdx.y * 64;
    int tx = tid & 15;
    int ty = tid >> 4;

    float acc[4][4];
#pragma unroll
    for (int i = 0; i < 4; i++)
#pragma unroll
        for (int j = 0; j < 4; j++)
            acc[i][j] = 0.f;

    int m = tid & 63;            // row this thread loads (same every j)
    int kq0 = tid >> 6;          // 0..3

    for (int kc = 0; kc < 2; kc++) {
        int k0 = kc * 64;
        // load + transpose into smem: As[k][m] = A[n0+m][k0+k]
#pragma unroll
        for (int j = 0; j < 4; j++) {
            int kq = kq0 + j * 4;                    // 0..15
            float4 av = *(const float4*)(A + (size_t)(n0 + m) * C_DIM + k0 + kq * 4);
            float4 wv = *(const float4*)(W + (size_t)(c0 + m) * C_DIM + k0 + kq * 4);
            As[kq * 4 + 0][m] = av.x; As[kq * 4 + 1][m] = av.y;
            As[kq * 4 + 2][m] = av.z; As[kq * 4 + 3][m] = av.w;
            Ws[kq * 4 + 0][m] = wv.x; Ws[kq * 4 + 1][m] = wv.y;
            Ws[kq * 4 + 2][m] = wv.z; Ws[kq * 4 + 3][m] = wv.w;
        }
        __syncthreads();
#pragma unroll
        for (int k = 0; k < 64; k++) {
            float4 a4 = *(const float4*)&As[k][ty * 4];
            float4 b4 = *(const float4*)&Ws[k][tx * 4];
            float a[4] = { a4.x, a4.y, a4.z, a4.w };
            float b[4] = { b4.x, b4.y, b4.z, b4.w };
#pragma unroll
            for (int i = 0; i < 4; i++)
#pragma unroll
                for (int j = 0; j < 4; j++)
                    acc[i][j] += a[i] * b[j];
        }
        __syncthreads();
    }
#pragma unroll
    for (int i = 0; i < 4; i++) {
        float4 o;
        float b0 = bias ? bias[c0 + tx * 4 + 0] : 0.f;
        float b1 = bias ? bias[c0 + tx * 4 + 1] : 0.f;
        float b2 = bias ? bias[c0 + tx * 4 + 2] : 0.f;
        float b3 = bias ? bias[c0 + tx * 4 + 3] : 0.f;
        o.x = acc[i][0] + b0; o.y = acc[i][1] + b1;
        o.z = acc[i][2] + b2; o.w = acc[i][3] + b3;
        *(float4*)(O + (size_t)(n0 + ty * 4 + i) * C_DIM + c0 + tx * 4) = o;
    }
}

__global__ void qkv_gemm_kernel(const float* __restrict__ x,
                                const float* __restrict__ Wq,
                                const float* __restrict__ Wk,
                                const float* __restrict__ Wv) {
    const float* W = (blockIdx.z == 0) ? Wq : (blockIdx.z == 1) ? Wk : Wv;
    float* O = (blockIdx.z == 0) ? g_Q : (blockIdx.z == 1) ? g_K : g_V;
    gemm64_tile(x, W, nullptr, O);
}

__global__ void ptable_gemm_kernel(const float* __restrict__ Wpos,
                                   const float* __restrict__ bpos) {
    gemm64_tile(g_PE, Wpos, bpos, g_P);
}

__global__ void out_gemm_kernel(const float* __restrict__ Wout,
                                float* __restrict__ out) {
    gemm64_tile(g_outpre, Wout, nullptr, out);
}

// ---------------------------------------------------------------------------
// Attention: one block per (h, a-group of 8). 256 threads.
__global__ void attn_kernel(const int* __restrict__ seq,
                            const float* __restrict__ param,
                            const float* __restrict__ conv_b,
                            float* __restrict__ attn_out) {
    int h = blockIdx.x >> 7;
    int ag = blockIdx.x & 127;
    int a0 = ag * 8;
    int tid = threadIdx.x;
    int lane = tid & 31;
    int wid = tid >> 5;

    __shared__ float4 qs4[8][4];        // 8 q vectors (16 floats each)
    __shared__ int   srow[1024];        // full seq row i
    __shared__ float probs[8][1024];    // 32KB: logits -> exp values
    __shared__ float wred[8][8];
    __shared__ float gmaxs[8];
    __shared__ float ginv[8];
    __shared__ float4 part4[8][8][4];   // [warp][r][d4]

    if (tid < 128) ((float*)qs4)[tid] = g_Q[h * 16384 + a0 * D_HEAD + tid];
    {
        int i = h * 128 + ag;
#pragma unroll
        for (int j = 0; j < 4; j++)
            srow[tid + j * 256] = seq[(size_t)i * N_NODES + tid + j * 256];
    }
    __syncthreads();

    const float SCALE = 0.0883883476483184f;  // 1/sqrt(128)
    float prm = param[0];
    float cb  = conv_b[0];
    float lmax[8];
#pragma unroll
    for (int r = 0; r < 8; r++) lmax[r] = -1e30f;

    const float4* Kh = (const float4*)(g_K + h * 16384);
#pragma unroll
    for (int t = 0; t < 4; t++) {
        int b = tid + t * 256;
        float4 k0 = Kh[b * 4 + 0], k1 = Kh[b * 4 + 1];
        float4 k2 = Kh[b * 4 + 2], k3 = Kh[b * 4 + 3];
        int oct = b >> 3;
        int seg = (b & 7) * 4;           // float4 offset within P row
#pragma unroll
        for (int r = 0; r < 8; r++) {
            int s = srow[r * 128 + oct];
            const float4* pr = (const float4*)(g_P + s * C_DIM) + seg;
            float4 p0 = pr[0], p1 = pr[1], p2 = pr[2], p3 = pr[3];
            float4 q0 = qs4[r][0], q1 = qs4[r][1], q2 = qs4[r][2], q3 = qs4[r][3];
            float cont = q0.x*k0.x + q0.y*k0.y + q0.z*k0.z + q0.w*k0.w
                       + q1.x*k1.x + q1.y*k1.y + q1.z*k1.z + q1.w*k1.w
                       + q2.x*k2.x + q2.y*k2.y + q2.z*k2.z + q2.w*k2.w
                       + q3.x*k3.x + q3.y*k3.y + q3.z*k3.z + q3.w*k3.w;
            float pos  = q0.x*p0.x + q0.y*p0.y + q0.z*p0.z + q0.w*p0.w
                       + q1.x*p1.x + q1.y*p1.y + q1.z*p1.z + q1.w*p1.w
                       + q2.x*p2.x + q2.y*p2.y + q2.z*p2.z + q2.w*p2.w
                       + q3.x*p3.x + q3.y*p3.y + q3.z*p3.z + q3.w*p3.w;
            float cv = g_conv[(size_t)(a0 + r) * N_NODES + b];
            float lg = (cont + pos) * SCALE + prm * (cv + cb);
            probs[r][b] = lg;
            lmax[r] = fmaxf(lmax[r], lg);
        }
    }
    // block max per r
#pragma unroll
    for (int r = 0; r < 8; r++) {
        float v = lmax[r];
#pragma unroll
        for (int o = 16; o > 0; o >>= 1) v = fmaxf(v, __shfl_xor_sync(~0u, v, o));
        if (lane == 0) wred[r][wid] = v;
    }
    __syncthreads();
    if (tid < 64) {
        int r = tid >> 3, k = tid & 7;
        float v = wred[r][k];
#pragma unroll
        for (int o = 4; o > 0; o >>= 1) v = fmaxf(v, __shfl_xor_sync(~0u, v, o));
        if (k == 0) gmaxs[r] = v;
    }
    __syncthreads();

    // exp + sum
    float lsum[8];
#pragma unroll
    for (int r = 0; r < 8; r++) lsum[r] = 0.f;
#pragma unroll
    for (int t = 0; t < 4; t++) {
        int b = tid + t * 256;
#pragma unroll
        for (int r = 0; r < 8; r++) {
            float e = __expf(probs[r][b] - gmaxs[r]);
            probs[r][b] = e;
            lsum[r] += e;
        }
    }
#pragma unroll
    for (int r = 0; r < 8; r++) {
        float v = lsum[r];
#pragma unroll
        for (int o = 16; o > 0; o >>= 1) v += __shfl_xor_sync(~0u, v, o);
        if (lane == 0) wred[r][wid] = v;
    }
    __syncthreads();
    if (tid < 64) {
        int r = tid >> 3, k = tid & 7;
        float v = wred[r][k];
#pragma unroll
        for (int o = 4; o > 0; o >>= 1) v += __shfl_xor_sync(~0u, v, o);
        if (k == 0) ginv[r] = 1.f / v;
    }
    __syncthreads();

    // write normalized attn rows with streaming stores (probs keeps e)
    float inv[8];
#pragma unroll
    for (int r = 0; r < 8; r++) inv[r] = ginv[r];
    float* aout = attn_out + ((size_t)h << 20) + ((size_t)a0 << 10);
#pragma unroll
    for (int t = 0; t < 4; t++) {
        int b = tid + t * 256;
#pragma unroll
        for (int r = 0; r < 8; r++)
            __stcs(&aout[((size_t)r << 10) + b], probs[r][b] * inv[r]);
    }

    // V phase: thread (bg, d4), bg = tid>>2 in [0,64), d4 = tid&3
    int d4 = tid & 3;
    int bg = tid >> 2;
    float4 acc[8];
#pragma unroll
    for (int r = 0; r < 8; r++) acc[r] = make_float4(0.f, 0.f, 0.f, 0.f);
    const float4* Vh = (const float4*)(g_V + h * 16384);
#pragma unroll
    for (int t = 0; t < 16; t++) {
        int b = bg + t * 64;
        float4 v4 = Vh[b * 4 + d4];
#pragma unroll
        for (int r = 0; r < 8; r++) {
            float e = probs[r][b];
            acc[r].x += e * v4.x; acc[r].y += e * v4.y;
            acc[r].z += e * v4.z; acc[r].w += e * v4.w;
        }
    }
#pragma unroll
    for (int r = 0; r < 8; r++) {
#pragma unroll
        for (int o = 16; o >= 4; o >>= 1) {
            acc[r].x += __shfl_xor_sync(~0u, acc[r].x, o);
            acc[r].y += __shfl_xor_sync(~0u, acc[r].y, o);
            acc[r].z += __shfl_xor_sync(~0u, acc[r].z, o);
            acc[r].w += __shfl_xor_sync(~0u, acc[r].w, o);
        }
    }
    if (lane < 4) {
#pragma unroll
        for (int r = 0; r < 8; r++) part4[wid][r][d4] = acc[r];
    }
    __syncthreads();
    if (tid < 128) {
        int r = tid >> 4, d = tid & 15;
        int dq = d >> 2, cmp = d & 3;
        float s = 0.f;
#pragma unroll
        for (int w = 0; w < 8; w++) s += ((const float*)&part4[w][r][dq])[cmp];
        g_outpre[h * 16384 + (a0 + r) * D_HEAD + d] = s * ginv[r];
    }
}

// ---------------------------------------------------------------------------
extern "C" void kernel_launch(void* const* d_in, const int* in_sizes, int n_in,
                              void* d_out, int out_size) {
    const float* x      = (const float*)d_in[0];
    const float* sign   = (const float*)d_in[1];
    const float* weight = (const float*)d_in[2];
    const float* Wq     = (const float*)d_in[3];
    const float* Wk     = (const float*)d_in[4];
    const float* Wv     = (const float*)d_in[5];
    const float* Wout   = (const float*)d_in[6];
    const float* Wpos   = (const float*)d_in[7];
    const float* bpos   = (const float*)d_in[8];
    const float* conv_w = (const float*)d_in[9];
    const float* conv_b = (const float*)d_in[10];
    const float* param  = (const float*)d_in[11];
    const int*   seq    = (const int*)d_in[12];
    const int*   ei     = (const int*)d_in[13];

    float* out  = (float*)d_out;              // [1024, 128]
    float* attn = out + N_NODES * C_DIM;      // [1, 8, 1024, 1024]

    zero_conv_kernel<<<NN / 4 / 256, 256>>>();
    pe_kernel<<<SEQ_MAX * C_DIM / 256, 256>>>();
    scatter_conv_kernel<<<E_EDGES / 256, 256>>>(ei, sign, weight, conv_w);
    qkv_gemm_kernel<<<dim3(16, 2, 3), 256>>>(x, Wq, Wk, Wv);
    ptable_gemm_kernel<<<dim3(8, 2), 256>>>(Wpos, bpos);
    attn_kernel<<<H_HEADS * 128, 256>>>(seq, param, conv_b, attn);
    out_gemm_kernel<<<dim3(16, 2), 256>>>(Wout, out);
}